// round 13
// baseline (speedup 1.0000x reference)
#include <cuda_runtime.h>
#include <cstdint>

#define BINS    10
#define BLOCK   256
#define STAGES  3
#define TILE_Q  512                        // quads per tile per array (2/thread)
#define TILE_B  (TILE_Q * 16)              // 8 KB per array per stage
#define MAXGRID 1024

// Per-block partials: every block writes only its own slot -> no init kernel.
__device__ float2       g_part[MAXGRID][BINS];
__device__ unsigned int g_arrive;   // zero at module load; last block resets it

// Dynamic smem: TMA staging for pred+targ only, then histogram banks.
//   float4 stage[STAGES][2][TILE_Q]            (48 KB)
//   float2 s_acc[2][BINS*BLOCK]                (40 KB)   -> 88 KB, 2 blocks/SM
#define SMEM_BYTES ((STAGES * 2 * TILE_B) + (2 * BINS * BLOCK * 8))

__device__ __forceinline__ unsigned smem_u32(const void* p) {
    return (unsigned)__cvta_generic_to_shared(p);
}
__device__ __forceinline__ void mbar_init(unsigned mbar, unsigned count) {
    asm volatile("mbarrier.init.shared.b64 [%0], %1;" :: "r"(mbar), "r"(count) : "memory");
}
__device__ __forceinline__ void mbar_expect_tx(unsigned mbar, unsigned bytes) {
    asm volatile("mbarrier.arrive.expect_tx.shared.b64 _, [%0], %1;"
                 :: "r"(mbar), "r"(bytes) : "memory");
}
__device__ __forceinline__ void mbar_wait(unsigned mbar, unsigned phase) {
    asm volatile(
        "{\n\t"
        ".reg .pred P;\n\t"
        "WAIT_%=:\n\t"
        "mbarrier.try_wait.parity.acquire.cta.shared::cta.b64 P, [%0], %1, 0x989680;\n\t"
        "@P bra.uni DONE_%=;\n\t"
        "bra.uni WAIT_%=;\n\t"
        "DONE_%=:\n\t"
        "}" :: "r"(mbar), "r"(phase) : "memory");
}
// 1D TMA bulk copy global -> shared (SASS: UBLKCP). No tensor map needed.
__device__ __forceinline__ void bulk_g2s(unsigned dst, const void* src,
                                         unsigned bytes, unsigned mbar) {
    asm volatile(
        "cp.async.bulk.shared::cluster.global.mbarrier::complete_tx::bytes "
        "[%0], [%1], %2, [%3];"
        :: "r"(dst), "l"(src), "r"(bytes), "r"(mbar) : "memory");
}

__device__ __forceinline__ void process_elem(float x, float t, float lw,
                                             float2* slot) {
    float u   = __expf(-x);               // FMUL + MUFU.EX2
    float w1  = 1.0f + u;
    float s   = __fdividef(1.0f, w1);     // sigmoid via MUFU.RCP
    float sp  = x + __logf(w1);           // softplus(x) = x + ln(1+e^{-x})
    float g10 = fabsf(s - t) * (float)BINS;
    int bin   = (int)g10;                 // g10 >= 0 -> trunc == floor
    bin = bin > (BINS - 1) ? (BINS - 1) : bin;
    float bce = fmaf(-x, t, sp);          // softplus(x) - x*t
    float2 a  = slot[bin * BLOCK];        // LDS.64
    a.x += lw;                            // lw in {0,1} masks both sums
    a.y += bce * lw;
    slot[bin * BLOCK] = a;                // STS.64
}

__device__ __forceinline__ void do_quad(const float4* sp, int idx, float4 w,
                                        float2* slot0, float2* slot1) {
    float4 p = sp[idx];
    float4 t = sp[TILE_Q + idx];
    process_elem(p.x, t.x, w.x, slot0);
    process_elem(p.y, t.y, w.y, slot1);
    process_elem(p.z, t.z, w.z, slot0);
    process_elem(p.w, t.w, w.w, slot1);
}

__global__ void __launch_bounds__(BLOCK)
ghmc_fused(const float4* __restrict__ pred4,
           const float4* __restrict__ targ4,
           const float4* __restrict__ lw4,
           int nquads, float* __restrict__ out) {
    extern __shared__ char smem_raw[];
    float4* stage = (float4*)smem_raw;                    // [STAGES][2][TILE_Q]
    float2* s_acc = (float2*)(smem_raw + STAGES * 2 * TILE_B);
    __shared__ uint64_t mbar_full[STAGES];

    int tid = threadIdx.x;
    int bid = blockIdx.x;
    int g   = gridDim.x;

    #pragma unroll
    for (int b = 0; b < BINS; b++) {
        s_acc[b * BLOCK + tid]                = make_float2(0.f, 0.f);
        s_acc[BINS * BLOCK + b * BLOCK + tid] = make_float2(0.f, 0.f);
    }
    float2* slot0 = &s_acc[tid];
    float2* slot1 = &s_acc[BINS * BLOCK + tid];

    // Tiles of TILE_Q quads; this block owns tiles bid, bid+g, bid+2g, ...
    int NT   = (nquads + TILE_Q - 1) / TILE_Q;
    int nt_b = (bid < NT) ? (NT - bid + g - 1) / g : 0;

    if (tid == 0) {
        #pragma unroll
        for (int s = 0; s < STAGES; s++)
            mbar_init(smem_u32(&mbar_full[s]), 1u);
    }
    __syncthreads();   // barriers + zeroed histogram visible block-wide

    // ---- prologue: TMA-fill all STAGES buffers with pred+targ ----
    if (tid == 0) {
        #pragma unroll
        for (int s = 0; s < STAGES; s++) {
            if (s < nt_b) {
                int  q0 = (bid + s * g) * TILE_Q;
                int  qc = nquads - q0; if (qc > TILE_Q) qc = TILE_Q;
                unsigned bytes = (unsigned)qc * 16u;
                unsigned mb    = smem_u32(&mbar_full[s]);
                unsigned dst   = smem_u32(stage + (s * 2) * TILE_Q);
                mbar_expect_tx(mb, 2u * bytes);
                bulk_g2s(dst,          pred4 + q0, bytes, mb);
                bulk_g2s(dst + TILE_B, targ4 + q0, bytes, mb);
            }
        }
    }

    // ---- lw register prefetch for tile 0 (direct LDG path) ----
    float4 lwA = make_float4(0.f, 0.f, 0.f, 0.f), lwB = lwA;
    if (nt_b > 0) {
        int q0 = bid * TILE_Q;
        if (q0 + tid < nquads)         lwA = __ldcs(lw4 + q0 + tid);
        if (q0 + tid + BLOCK < nquads) lwB = __ldcs(lw4 + q0 + tid + BLOCK);
    }

    // ---- main loop: wait tile k, prefetch lw for k+1, process, refill k+S ----
    for (int k = 0; k < nt_b; k++) {
        int buf     = k % STAGES;
        unsigned mb = smem_u32(&mbar_full[buf]);
        mbar_wait(mb, (unsigned)((k / STAGES) & 1));

        float4 la = lwA, lb = lwB;
        int kn = k + 1;
        if (kn < nt_b) {   // issue next tile's lw loads before consuming k
            int qn = (bid + kn * g) * TILE_Q;
            lwA = make_float4(0.f, 0.f, 0.f, 0.f); lwB = lwA;
            if (qn + tid < nquads)         lwA = __ldcs(lw4 + qn + tid);
            if (qn + tid + BLOCK < nquads) lwB = __ldcs(lw4 + qn + tid + BLOCK);
        }

        int q0 = (bid + k * g) * TILE_Q;
        int qc = nquads - q0; if (qc > TILE_Q) qc = TILE_Q;
        const float4* sp = stage + (buf * 2) * TILE_Q;
        if (tid < qc)          do_quad(sp, tid,         la, slot0, slot1);
        if (tid + BLOCK < qc)  do_quad(sp, tid + BLOCK, lb, slot0, slot1);
        __syncthreads();   // whole block done with buffer k%S

        int kf = k + STAGES;
        if (tid == 0 && kf < nt_b) {
            int  fq0 = (bid + kf * g) * TILE_Q;
            int  fqc = nquads - fq0; if (fqc > TILE_Q) fqc = TILE_Q;
            unsigned bytes = (unsigned)fqc * 16u;
            unsigned dst   = smem_u32(stage + (buf * 2) * TILE_Q);
            mbar_expect_tx(mb, 2u * bytes);
            bulk_g2s(dst,          pred4 + fq0, bytes, mb);
            bulk_g2s(dst + TILE_B, targ4 + fq0, bytes, mb);
        }
    }
    __syncthreads();

    // Block tree-reduction; fold parity bank 1 into bank 0 on the first pass.
    if (tid < 128) {
        #pragma unroll
        for (int b = 0; b < BINS; b++) {
            float2 a = s_acc[b * BLOCK + tid];
            float2 c = s_acc[b * BLOCK + tid + 128];
            float2 d = s_acc[BINS * BLOCK + b * BLOCK + tid];
            float2 e = s_acc[BINS * BLOCK + b * BLOCK + tid + 128];
            a.x += c.x + d.x + e.x;
            a.y += c.y + d.y + e.y;
            s_acc[b * BLOCK + tid] = a;
        }
    }
    __syncthreads();
    for (int off = 64; off > 0; off >>= 1) {
        if (tid < off) {
            #pragma unroll
            for (int b = 0; b < BINS; b++) {
                float2 a = s_acc[b * BLOCK + tid];
                float2 c = s_acc[b * BLOCK + tid + off];
                a.x += c.x; a.y += c.y;
                s_acc[b * BLOCK + tid] = a;
            }
        }
        __syncthreads();
    }
    if (tid < BINS)
        g_part[bid][tid] = s_acc[tid * BLOCK];

    // ---- last-block-done finalize (deterministic: counter self-resets) ----
    __shared__ unsigned int s_ticket;
    __threadfence();
    if (tid == 0) s_ticket = atomicAdd(&g_arrive, 1u);
    __syncthreads();
    if (s_ticket != gridDim.x - 1) return;

    __threadfence();  // acquire all blocks' partial writes
    int lane = tid & 31, wid = tid >> 5;
    float2 acc[BINS];
    #pragma unroll
    for (int b = 0; b < BINS; b++) acc[b] = make_float2(0.f, 0.f);
    for (int k = tid; k < (int)gridDim.x; k += BLOCK) {
        #pragma unroll
        for (int b = 0; b < BINS; b++) {
            float2 v = g_part[k][b];
            acc[b].x += v.x; acc[b].y += v.y;
        }
    }
    #pragma unroll
    for (int b = 0; b < BINS; b++) {
        #pragma unroll
        for (int off = 16; off > 0; off >>= 1) {
            acc[b].x += __shfl_down_sync(0xffffffffu, acc[b].x, off);
            acc[b].y += __shfl_down_sync(0xffffffffu, acc[b].y, off);
        }
    }
    __shared__ float2 s_red[BLOCK / 32][BINS];
    if (lane == 0)
        #pragma unroll
        for (int b = 0; b < BINS; b++) s_red[wid][b] = acc[b];
    __syncthreads();
    if (tid == 0) {
        // loss = (1/n) * sum_b S[b]/counts[b]   (tot cancels exactly)
        double loss = 0.0;
        int n = 0;
        #pragma unroll
        for (int b = 0; b < BINS; b++) {
            double c = 0.0, s = 0.0;
            for (int w = 0; w < BLOCK / 32; w++) {
                c += (double)s_red[w][b].x;
                s += (double)s_red[w][b].y;
            }
            if (c > 0.0) { n++; loss += s / c; }
        }
        out[0] = (float)(n > 0 ? loss / (double)n : 0.0);
        g_arrive = 0u;   // pristine state for the next graph replay
    }
}

extern "C" void kernel_launch(void* const* d_in, const int* in_sizes, int n_in,
                              void* d_out, int out_size) {
    const float* pred = (const float*)d_in[0];
    const float* targ = (const float*)d_in[1];
    const float* lw   = (const float*)d_in[2];
    float* out = (float*)d_out;

    int n  = in_sizes[0];
    int nq = n / 4;   // N*C divisible by 4: no scalar tail

    static int attr_done = 0;
    if (!attr_done) {
        cudaFuncSetAttribute(ghmc_fused,
                             cudaFuncAttributeMaxDynamicSharedMemorySize,
                             SMEM_BYTES);
        attr_done = 1;
    }

    int grid = 296;   // 2 blocks/SM * 148 SMs (88 KB dynamic smem each)
    int max_grid = (nq + TILE_Q - 1) / TILE_Q;
    if (max_grid < 1) max_grid = 1;
    if (grid > max_grid) grid = max_grid;

    ghmc_fused<<<grid, BLOCK, SMEM_BYTES>>>((const float4*)pred,
                                            (const float4*)targ,
                                            (const float4*)lw, nq, out);
}

// round 16
// speedup vs baseline: 1.0625x; 1.0625x over previous
#include <cuda_runtime.h>
#include <cstdint>

#define BINS    10
#define BLOCK   256
#define STAGES  3
#define TILE_Q  512                        // quads per tile per array (2/thread)
#define TILE_B  (TILE_Q * 16)              // 8 KB per array per stage
#define MAXGRID 1024

// Per-block partials: every block writes only its own slot -> no init kernel.
__device__ float2       g_part[MAXGRID][BINS];
__device__ unsigned int g_arrive;   // zero at module load; last block resets it

// Dynamic smem: staging ring then histogram banks.
//   float4 stage[STAGES][3][TILE_Q]            (72 KB)
//   float2 s_acc[2][BINS*BLOCK]                (40 KB)   -> 112 KB, 2 blocks/SM
#define SMEM_BYTES ((STAGES * 3 * TILE_B) + (2 * BINS * BLOCK * 8))

__device__ __forceinline__ unsigned smem_u32(const void* p) {
    return (unsigned)__cvta_generic_to_shared(p);
}
__device__ __forceinline__ void mbar_init(unsigned mbar, unsigned count) {
    asm volatile("mbarrier.init.shared.b64 [%0], %1;" :: "r"(mbar), "r"(count) : "memory");
}
__device__ __forceinline__ void mbar_expect_tx(unsigned mbar, unsigned bytes) {
    asm volatile("mbarrier.arrive.expect_tx.shared.b64 _, [%0], %1;"
                 :: "r"(mbar), "r"(bytes) : "memory");
}
__device__ __forceinline__ void mbar_wait(unsigned mbar, unsigned phase) {
    asm volatile(
        "{\n\t"
        ".reg .pred P;\n\t"
        "WAIT_%=:\n\t"
        "mbarrier.try_wait.parity.acquire.cta.shared::cta.b64 P, [%0], %1, 0x989680;\n\t"
        "@P bra.uni DONE_%=;\n\t"
        "bra.uni WAIT_%=;\n\t"
        "DONE_%=:\n\t"
        "}" :: "r"(mbar), "r"(phase) : "memory");
}
// 1D TMA bulk copy global -> shared (SASS: UBLKCP). No tensor map needed.
__device__ __forceinline__ void bulk_g2s(unsigned dst, const void* src,
                                         unsigned bytes, unsigned mbar) {
    asm volatile(
        "cp.async.bulk.shared::cluster.global.mbarrier::complete_tx::bytes "
        "[%0], [%1], %2, [%3];"
        :: "r"(dst), "l"(src), "r"(bytes), "r"(mbar) : "memory");
}

__device__ __forceinline__ void process_elem(float x, float t, float lw,
                                             float2* slot) {
    float u   = __expf(-x);               // FMUL + MUFU.EX2
    float w1  = 1.0f + u;
    float s   = __fdividef(1.0f, w1);     // sigmoid via MUFU.RCP
    float sp  = x + __logf(w1);           // softplus(x) = x + ln(1+e^{-x})
    float g10 = fabsf(s - t) * (float)BINS;
    int bin   = (int)g10;                 // g10 >= 0 -> trunc == floor
    bin = bin > (BINS - 1) ? (BINS - 1) : bin;
    float bce = fmaf(-x, t, sp);          // softplus(x) - x*t
    float2 a  = slot[bin * BLOCK];        // LDS.64
    a.x += lw;                            // lw in {0,1} masks both sums
    a.y += bce * lw;
    slot[bin * BLOCK] = a;                // STS.64
}

__device__ __forceinline__ void do_quad(const float4* sp, int idx,
                                        float2* slot0, float2* slot1) {
    float4 p = sp[idx];
    float4 t = sp[TILE_Q + idx];
    float4 w = sp[2 * TILE_Q + idx];
    process_elem(p.x, t.x, w.x, slot0);
    process_elem(p.y, t.y, w.y, slot1);
    process_elem(p.z, t.z, w.z, slot0);
    process_elem(p.w, t.w, w.w, slot1);
}

__global__ void __launch_bounds__(BLOCK)
ghmc_fused(const float4* __restrict__ pred4,
           const float4* __restrict__ targ4,
           const float4* __restrict__ lw4,
           int nquads, float* __restrict__ out) {
    extern __shared__ char smem_raw[];
    float4* stage = (float4*)smem_raw;                    // [STAGES][3][TILE_Q]
    float2* s_acc = (float2*)(smem_raw + STAGES * 3 * TILE_B);
    __shared__ uint64_t mbar_full[STAGES];

    int tid = threadIdx.x;
    int bid = blockIdx.x;
    int g   = gridDim.x;

    #pragma unroll
    for (int b = 0; b < BINS; b++) {
        s_acc[b * BLOCK + tid]                = make_float2(0.f, 0.f);
        s_acc[BINS * BLOCK + b * BLOCK + tid] = make_float2(0.f, 0.f);
    }
    float2* slot0 = &s_acc[tid];
    float2* slot1 = &s_acc[BINS * BLOCK + tid];

    // Tiles of TILE_Q quads; this block owns tiles bid, bid+g, bid+2g, ...
    int NT   = (nquads + TILE_Q - 1) / TILE_Q;
    int nt_b = (bid < NT) ? (NT - bid + g - 1) / g : 0;

    if (tid == 0) {
        #pragma unroll
        for (int s = 0; s < STAGES; s++)
            mbar_init(smem_u32(&mbar_full[s]), 1u);
    }
    __syncthreads();   // barriers + zeroed histogram visible block-wide

    // ---- prologue: fill all STAGES buffers (tiles 0..S-1 of this block) ----
    if (tid == 0) {
        #pragma unroll
        for (int s = 0; s < STAGES; s++) {
            if (s < nt_b) {
                int  q0 = (bid + s * g) * TILE_Q;
                int  qc = nquads - q0; if (qc > TILE_Q) qc = TILE_Q;
                unsigned bytes = (unsigned)qc * 16u;
                unsigned mb    = smem_u32(&mbar_full[s]);
                unsigned dst   = smem_u32(stage + (s * 3) * TILE_Q);
                mbar_expect_tx(mb, 3u * bytes);
                bulk_g2s(dst,              pred4 + q0, bytes, mb);
                bulk_g2s(dst + TILE_B,     targ4 + q0, bytes, mb);
                bulk_g2s(dst + 2 * TILE_B, lw4   + q0, bytes, mb);
            }
        }
    }

    // ---- main loop: wait tile k, process 2 quads/thread, refill with k+S ----
    for (int k = 0; k < nt_b; k++) {
        int buf     = k % STAGES;
        unsigned mb = smem_u32(&mbar_full[buf]);
        mbar_wait(mb, (unsigned)((k / STAGES) & 1));

        int q0 = (bid + k * g) * TILE_Q;
        int qc = nquads - q0; if (qc > TILE_Q) qc = TILE_Q;
        const float4* sp = stage + (buf * 3) * TILE_Q;
        if (tid < qc)          do_quad(sp, tid,          slot0, slot1);
        if (tid + BLOCK < qc)  do_quad(sp, tid + BLOCK,  slot0, slot1);
        __syncthreads();   // whole block done with buffer k%S

        int kf = k + STAGES;
        if (tid == 0 && kf < nt_b) {
            int  fq0 = (bid + kf * g) * TILE_Q;
            int  fqc = nquads - fq0; if (fqc > TILE_Q) fqc = TILE_Q;
            unsigned bytes = (unsigned)fqc * 16u;
            unsigned dst   = smem_u32(stage + (buf * 3) * TILE_Q);
            mbar_expect_tx(mb, 3u * bytes);
            bulk_g2s(dst,              pred4 + fq0, bytes, mb);
            bulk_g2s(dst + TILE_B,     targ4 + fq0, bytes, mb);
            bulk_g2s(dst + 2 * TILE_B, lw4   + fq0, bytes, mb);
        }
    }
    __syncthreads();

    // Lean epilogue: fold both banks + offset-128 in one pass, tree to 32,
    // then single-warp shuffle (no further syncthreads).
    if (tid < 128) {
        #pragma unroll
        for (int b = 0; b < BINS; b++) {
            float2 a = s_acc[b * BLOCK + tid];
            float2 c = s_acc[b * BLOCK + tid + 128];
            float2 d = s_acc[BINS * BLOCK + b * BLOCK + tid];
            float2 e = s_acc[BINS * BLOCK + b * BLOCK + tid + 128];
            a.x += c.x + d.x + e.x;
            a.y += c.y + d.y + e.y;
            s_acc[b * BLOCK + tid] = a;
        }
    }
    __syncthreads();
    if (tid < 64) {
        #pragma unroll
        for (int b = 0; b < BINS; b++) {
            float2 a = s_acc[b * BLOCK + tid];
            float2 c = s_acc[b * BLOCK + tid + 64];
            a.x += c.x; a.y += c.y;
            s_acc[b * BLOCK + tid] = a;
        }
    }
    __syncthreads();
    if (tid < 32) {
        #pragma unroll
        for (int b = 0; b < BINS; b++) {
            float2 a = s_acc[b * BLOCK + tid];
            float2 c = s_acc[b * BLOCK + tid + 32];
            float cx = a.x + c.x, cy = a.y + c.y;
            #pragma unroll
            for (int off = 16; off > 0; off >>= 1) {
                cx += __shfl_down_sync(0xffffffffu, cx, off);
                cy += __shfl_down_sync(0xffffffffu, cy, off);
            }
            if (tid == 0) g_part[bid][b] = make_float2(cx, cy);
        }
    }

    // ---- last-block-done finalize (deterministic: counter self-resets) ----
    __shared__ unsigned int s_ticket;
    __threadfence();
    if (tid == 0) s_ticket = atomicAdd(&g_arrive, 1u);
    __syncthreads();
    if (s_ticket != gridDim.x - 1) return;

    __threadfence();  // acquire all blocks' partial writes
    int lane = tid & 31, wid = tid >> 5;
    float2 acc[BINS];
    #pragma unroll
    for (int b = 0; b < BINS; b++) acc[b] = make_float2(0.f, 0.f);
    for (int k = tid; k < (int)gridDim.x; k += BLOCK) {
        #pragma unroll
        for (int b = 0; b < BINS; b++) {
            float2 v = g_part[k][b];
            acc[b].x += v.x; acc[b].y += v.y;
        }
    }
    #pragma unroll
    for (int b = 0; b < BINS; b++) {
        #pragma unroll
        for (int off = 16; off > 0; off >>= 1) {
            acc[b].x += __shfl_down_sync(0xffffffffu, acc[b].x, off);
            acc[b].y += __shfl_down_sync(0xffffffffu, acc[b].y, off);
        }
    }
    __shared__ float2 s_red[BLOCK / 32][BINS];
    if (lane == 0)
        #pragma unroll
        for (int b = 0; b < BINS; b++) s_red[wid][b] = acc[b];
    __syncthreads();
    if (tid == 0) {
        // loss = (1/n) * sum_b S[b]/counts[b]   (tot cancels exactly)
        double loss = 0.0;
        int n = 0;
        #pragma unroll
        for (int b = 0; b < BINS; b++) {
            double c = 0.0, s = 0.0;
            for (int w = 0; w < BLOCK / 32; w++) {
                c += (double)s_red[w][b].x;
                s += (double)s_red[w][b].y;
            }
            if (c > 0.0) { n++; loss += s / c; }
        }
        out[0] = (float)(n > 0 ? loss / (double)n : 0.0);
        g_arrive = 0u;   // pristine state for the next graph replay
    }
}

extern "C" void kernel_launch(void* const* d_in, const int* in_sizes, int n_in,
                              void* d_out, int out_size) {
    const float* pred = (const float*)d_in[0];
    const float* targ = (const float*)d_in[1];
    const float* lw   = (const float*)d_in[2];
    float* out = (float*)d_out;

    int n  = in_sizes[0];
    int nq = n / 4;   // N*C divisible by 4: no scalar tail

    static int attr_done = 0;
    if (!attr_done) {
        cudaFuncSetAttribute(ghmc_fused,
                             cudaFuncAttributeMaxDynamicSharedMemorySize,
                             SMEM_BYTES);
        attr_done = 1;
    }

    int grid = 296;   // 2 blocks/SM * 148 SMs (112 KB dynamic smem each)
    int max_grid = (nq + TILE_Q - 1) / TILE_Q;
    if (max_grid < 1) max_grid = 1;
    if (grid > max_grid) grid = max_grid;

    ghmc_fused<<<grid, BLOCK, SMEM_BYTES>>>((const float4*)pred,
                                            (const float4*)targ,
                                            (const float4*)lw, nq, out);
}